// round 3
// baseline (speedup 1.0000x reference)
#include <cuda_runtime.h>
#include <cstdint>

#define NN 100000
#define NH 20000
#define NE 800000
#define NKA (NH*2)     // hedge-type keys
#define NKB (NN*2)     // node-type keys

// ---------------- static device buffers ------------------------------------
__device__ __align__(16) float g_ef[(size_t)NH*128];
__device__ __align__(16) float g_no[(size_t)NN*128];
__device__ __align__(16) float g_xl[(size_t)NN*128];
__device__ __align__(16) float g_h[(size_t)NN*64];
__device__ int g_cntA[NKA], g_offA[NKA], g_curA[NKA];
__device__ int g_cntB[NKB], g_offB[NKB], g_curB[NKB];
__device__ int g_sortA[NE];   // node ids, sorted by (hedge,type)
__device__ int g_sortB[NE];   // ef row offsets, sorted by (node,type)
// Pre-swizzled tf32 B-images
__device__ __align__(16) float g_Bxl[2*128*32];
__device__ __align__(16) float g_Bmix[4*64*32];
__device__ __align__(16) float g_Bgru[4*256*32];
__device__ float g_bias[256];
__device__ float g_bcmix[64];

// ---------------- helpers ---------------------------------------------------
__device__ __forceinline__ float to_tf32(float v) {
    uint32_t u; asm("cvt.rna.tf32.f32 %0, %1;" : "=r"(u) : "f"(v));
    return __uint_as_float(u);
}
__device__ __forceinline__ int swz(int kk, int row) {
    int r = kk & 7;
    int pos = (r < 4) ? (r * 2) : ((r - 4) * 2 + 1);
    int sc = (kk & 24) + pos;
    return (sc + ((row & 3) << 3)) & 31;
}
__device__ __forceinline__ void mma_tf32(float* c, const uint32_t* a,
                                         uint32_t b0, uint32_t b1) {
    asm volatile(
        "mma.sync.aligned.m16n8k8.row.col.f32.tf32.tf32.f32 "
        "{%0,%1,%2,%3}, {%4,%5,%6,%7}, {%8,%9}, {%0,%1,%2,%3};"
        : "+f"(c[0]), "+f"(c[1]), "+f"(c[2]), "+f"(c[3])
        : "r"(a[0]), "r"(a[1]), "r"(a[2]), "r"(a[3]), "r"(b0), "r"(b1));
}
__device__ __forceinline__ float sigf(float x) { return 1.f / (1.f + __expf(-x)); }
__device__ __forceinline__ float tanh_fast(float x) {
    return 1.f - 2.f / (__expf(2.f * x) + 1.f);
}

// ---------------- zero counters ---------------------------------------------
__global__ void k_zero_cnt() {
    int i = blockIdx.x * 256 + threadIdx.x;
    if (i < NKA) g_cntA[i] = 0;
    if (i < NKB) g_cntB[i] = 0;
}

// ---------------- histogram -------------------------------------------------
__global__ void k_hist(const int* __restrict__ ni, const int* __restrict__ hi,
                       const int* __restrict__ ea) {
    int e = blockIdx.x * 256 + threadIdx.x;
    if (e >= NE) return;
    int t = ea[e];
    atomicAdd(&g_cntA[hi[e] * 2 + t], 1);
    atomicAdd(&g_cntB[ni[e] * 2 + t], 1);
}

// ---------------- scan (2 blocks, chunked) ----------------------------------
__global__ __launch_bounds__(1024) void k_scan() {
    __shared__ int sm[1024];
    int tid = threadIdx.x;
    const int* cnt; int* off; int* cur; int n;
    if (blockIdx.x == 0) { cnt = g_cntA; off = g_offA; cur = g_curA; n = NKA; }
    else                 { cnt = g_cntB; off = g_offB; cur = g_curB; n = NKB; }
    int chunk = (n + 1023) >> 10;
    int s0 = tid * chunk, s1 = min(s0 + chunk, n);
    int sum = 0;
    for (int i = s0; i < s1; i++) sum += cnt[i];
    sm[tid] = sum;
    __syncthreads();
    for (int d = 1; d < 1024; d <<= 1) {
        int v = (tid >= d) ? sm[tid - d] : 0;
        __syncthreads();
        sm[tid] += v;
        __syncthreads();
    }
    int run = sm[tid] - sum;
    for (int i = s0; i < s1; i++) {
        off[i] = run; cur[i] = run;
        run += cnt[i];
    }
}

// ---------------- permute: build both sorted lists --------------------------
__global__ void k_perm(const int* __restrict__ ni, const int* __restrict__ hi,
                       const int* __restrict__ ea) {
    int e = blockIdx.x * 256 + threadIdx.x;
    if (e >= NE) return;
    int n = ni[e], h = hi[e], t = ea[e];
    int pA = atomicAdd(&g_curA[h * 2 + t], 1);
    g_sortA[pA] = n;
    int pB = atomicAdd(&g_curB[n * 2 + t], 1);
    g_sortB[pB] = h * 128 + t * 64;
}

// ---------------- prep: swizzled tf32 B-images + biases ---------------------
__global__ void k_prep(const float* __restrict__ Wc, const float* __restrict__ Wmix,
                       const float* __restrict__ bmix, const float* __restrict__ bconv,
                       const float* __restrict__ Wih, const float* __restrict__ Whh,
                       const float* __restrict__ bih, const float* __restrict__ bhh) {
    int idx = blockIdx.x * blockDim.x + threadIdx.x;
    if (idx < 8192) {                     // Bxl: [2][128][32]
        int kc = idx >> 12, rem = idx & 4095, c = rem >> 5, kk = rem & 31;
        int k = kc * 32 + kk;
        int t = c >> 6, j = c & 63;
        g_Bxl[(kc * 128 + c) * 32 + swz(kk, c)] = to_tf32(Wc[t * 4096 + k * 64 + j]);
    } else if (idx < 16384) {             // Bmix: [4][64][32]
        int i = idx - 8192;
        int kc = i >> 11, rem = i & 2047, c = rem >> 5, kk = rem & 31;
        int k = kc * 32 + kk;
        g_Bmix[(kc * 64 + c) * 32 + swz(kk, c)] = to_tf32(Wmix[k * 64 + c]);
    } else if (idx < 49152) {             // Bgru: [4][256][32], c = j*4+seg
        int i = idx - 16384;
        int kc = i >> 13, rem = i & 8191, c = rem >> 5, kk = rem & 31;
        int k = kc * 32 + kk;
        int j = c >> 2, seg = c & 3;
        float v = 0.f;
        if (k < 64) {
            if (seg == 0)      v = Wih[k * 192 + j];
            else if (seg == 1) v = Wih[k * 192 + 64 + j];
            else if (seg == 2) v = Wih[k * 192 + 128 + j];
        } else {
            int k2 = k - 64;
            if (seg == 0)      v = Whh[k2 * 192 + j];
            else if (seg == 1) v = Whh[k2 * 192 + 64 + j];
            else if (seg == 3) v = Whh[k2 * 192 + 128 + j];
        }
        g_Bgru[(kc * 256 + c) * 32 + swz(kk, c)] = to_tf32(v);
    } else if (idx < 49152 + 256) {       // GRU bias (seg-major)
        int c = idx - 49152;
        int seg = c >> 6, j = c & 63;
        float b;
        if (seg == 0)      b = bih[j] + bhh[j];
        else if (seg == 1) b = bih[64 + j] + bhh[64 + j];
        else if (seg == 2) b = bih[128 + j];
        else               b = bhh[128 + j];
        g_bias[c] = b;
    } else if (idx < 49152 + 256 + 64) {  // folded mix bias
        int j = idx - 49152 - 256;
        float s = bmix[j];
        for (int k = 0; k < 128; k++) s += bconv[k] * Wmix[k * 64 + j];
        g_bcmix[j] = s;
    }
}

// ---------------- GEMM 1: xl = x @ [Wc0|Wc1] --------------------------------
__global__ __launch_bounds__(256) void k_mma_xl(const float* __restrict__ x) {
    __shared__ __align__(16) float As[128][32];
    __shared__ __align__(16) float Bs[128][32];
    int tid = threadIdx.x;
    int lane = tid & 31, warp = tid >> 5;
    int warpM = warp >> 1, warpN = warp & 1;
    int g = lane >> 2, t = lane & 3;
    int rot = (g & 3) << 3;
    int n0 = blockIdx.x * 128;
    float acc[2][8][4] = {};
    for (int kc = 0; kc < 2; kc++) {
        __syncthreads();
        for (int i = tid; i < 4096; i += 256) {
            int m = i >> 5, kk = i & 31;
            int n = n0 + m;
            float v = (n < NN) ? x[(size_t)n * 64 + kc * 32 + kk] : 0.f;
            As[m][swz(kk, m)] = to_tf32(v);
        }
        const float4* src = (const float4*)&g_Bxl[kc * 4096];
        float4* dst = (float4*)&Bs[0][0];
        for (int i = tid; i < 1024; i += 256) dst[i] = src[i];
        __syncthreads();
#pragma unroll
        for (int s = 0; s < 4; s++) {
            int pc = (s * 8 + 2 * t + rot) & 31;
            uint32_t a[2][4];
#pragma unroll
            for (int mt = 0; mt < 2; mt++) {
                int r = warpM * 32 + mt * 16 + g;
                float2 lo = *(const float2*)&As[r][pc];
                float2 hi = *(const float2*)&As[r + 8][pc];
                a[mt][0] = __float_as_uint(lo.x); a[mt][1] = __float_as_uint(hi.x);
                a[mt][2] = __float_as_uint(lo.y); a[mt][3] = __float_as_uint(hi.y);
            }
#pragma unroll
            for (int nt = 0; nt < 8; nt++) {
                int c = warpN * 64 + nt * 8 + g;
                float2 b = *(const float2*)&Bs[c][pc];
                uint32_t b0 = __float_as_uint(b.x), b1 = __float_as_uint(b.y);
                mma_tf32(acc[0][nt], a[0], b0, b1);
                mma_tf32(acc[1][nt], a[1], b0, b1);
            }
        }
    }
#pragma unroll
    for (int mt = 0; mt < 2; mt++) {
        int r = n0 + warpM * 32 + mt * 16 + g;
#pragma unroll
        for (int nt = 0; nt < 8; nt++) {
            int c = warpN * 64 + nt * 8 + 2 * t;
            if (r < NN)
                *(float2*)&g_xl[(size_t)r * 128 + c] =
                    make_float2(acc[mt][nt][0], acc[mt][nt][1]);
            if (r + 8 < NN)
                *(float2*)&g_xl[(size_t)(r + 8) * 128 + c] =
                    make_float2(acc[mt][nt][2], acc[mt][nt][3]);
        }
    }
}

// ---------------- gather A: ef[h,t] = Binv * sum xl[node,t] ------------------
__global__ __launch_bounds__(256) void k_gatherA() {
    int key = (blockIdx.x * 256 + threadIdx.x) >> 5;
    if (key >= NKA) return;
    int lane = threadIdx.x & 31;
    int t = key & 1, h = key >> 1;
    int base = g_offA[key], cnt = g_cntA[key];
    const float* xb = g_xl + t * 64 + lane * 2;
    float ax = 0.f, ay = 0.f;
    int i = 0;
    for (; i + 4 <= cnt; i += 4) {
        int n0 = g_sortA[base + i + 0];
        int n1 = g_sortA[base + i + 1];
        int n2 = g_sortA[base + i + 2];
        int n3 = g_sortA[base + i + 3];
        float2 v0 = *(const float2*)(xb + (size_t)n0 * 128);
        float2 v1 = *(const float2*)(xb + (size_t)n1 * 128);
        float2 v2 = *(const float2*)(xb + (size_t)n2 * 128);
        float2 v3 = *(const float2*)(xb + (size_t)n3 * 128);
        ax += (v0.x + v1.x) + (v2.x + v3.x);
        ay += (v0.y + v1.y) + (v2.y + v3.y);
    }
    for (; i < cnt; i++) {
        int n = g_sortA[base + i];
        float2 v = *(const float2*)(xb + (size_t)n * 128);
        ax += v.x; ay += v.y;
    }
    float s = (cnt > 0) ? 1.f / (float)cnt : 0.f;
    *(float2*)&g_ef[(size_t)h * 128 + t * 64 + lane * 2] = make_float2(ax * s, ay * s);
}

// ---------------- gather B: no[n,t] = Dinv * sum ef[h,t] ---------------------
__global__ __launch_bounds__(256) void k_gatherB() {
    int key = (blockIdx.x * 256 + threadIdx.x) >> 5;
    if (key >= NKB) return;
    int lane = threadIdx.x & 31;
    int t = key & 1, n = key >> 1;
    int base = g_offB[key], cnt = g_cntB[key];
    const float* eb = g_ef + lane * 2;
    float ax = 0.f, ay = 0.f;
    int i = 0;
    for (; i + 4 <= cnt; i += 4) {
        int o0 = g_sortB[base + i + 0];
        int o1 = g_sortB[base + i + 1];
        int o2 = g_sortB[base + i + 2];
        int o3 = g_sortB[base + i + 3];
        float2 v0 = *(const float2*)(eb + o0);
        float2 v1 = *(const float2*)(eb + o1);
        float2 v2 = *(const float2*)(eb + o2);
        float2 v3 = *(const float2*)(eb + o3);
        ax += (v0.x + v1.x) + (v2.x + v3.x);
        ay += (v0.y + v1.y) + (v2.y + v3.y);
    }
    for (; i < cnt; i++) {
        int o = g_sortB[base + i];
        float2 v = *(const float2*)(eb + o);
        ax += v.x; ay += v.y;
    }
    float s = (cnt > 0) ? 1.f / (float)cnt : 0.f;
    *(float2*)&g_no[(size_t)n * 128 + t * 64 + lane * 2] = make_float2(ax * s, ay * s);
}

// ---------------- GEMM 2: h = relu(no @ Wmix + bcmix) -----------------------
__global__ __launch_bounds__(256) void k_mma_mix() {
    __shared__ __align__(16) float As[128][32];
    __shared__ __align__(16) float Bs[64][32];
    int tid = threadIdx.x;
    int lane = tid & 31, warp = tid >> 5;
    int warpM = warp >> 1, warpN = warp & 1;
    int g = lane >> 2, t = lane & 3;
    int rot = (g & 3) << 3;
    int n0 = blockIdx.x * 128;
    float acc[2][4][4] = {};
    for (int kc = 0; kc < 4; kc++) {
        __syncthreads();
        for (int i = tid; i < 4096; i += 256) {
            int m = i >> 5, kk = i & 31;
            int n = n0 + m;
            float v = (n < NN) ? g_no[(size_t)n * 128 + kc * 32 + kk] : 0.f;
            As[m][swz(kk, m)] = to_tf32(v);
        }
        const float4* src = (const float4*)&g_Bmix[kc * 2048];
        float4* dst = (float4*)&Bs[0][0];
        for (int i = tid; i < 512; i += 256) dst[i] = src[i];
        __syncthreads();
#pragma unroll
        for (int s = 0; s < 4; s++) {
            int pc = (s * 8 + 2 * t + rot) & 31;
            uint32_t a[2][4];
#pragma unroll
            for (int mt = 0; mt < 2; mt++) {
                int r = warpM * 32 + mt * 16 + g;
                float2 lo = *(const float2*)&As[r][pc];
                float2 hi = *(const float2*)&As[r + 8][pc];
                a[mt][0] = __float_as_uint(lo.x); a[mt][1] = __float_as_uint(hi.x);
                a[mt][2] = __float_as_uint(lo.y); a[mt][3] = __float_as_uint(hi.y);
            }
#pragma unroll
            for (int nt = 0; nt < 4; nt++) {
                int c = warpN * 32 + nt * 8 + g;
                float2 b = *(const float2*)&Bs[c][pc];
                uint32_t b0 = __float_as_uint(b.x), b1 = __float_as_uint(b.y);
                mma_tf32(acc[0][nt], a[0], b0, b1);
                mma_tf32(acc[1][nt], a[1], b0, b1);
            }
        }
    }
#pragma unroll
    for (int mt = 0; mt < 2; mt++) {
        int r = n0 + warpM * 32 + mt * 16 + g;
#pragma unroll
        for (int nt = 0; nt < 4; nt++) {
            int c = warpN * 32 + nt * 8 + 2 * t;
            float b0 = g_bcmix[c], b1 = g_bcmix[c + 1];
            if (r < NN)
                *(float2*)&g_h[(size_t)r * 64 + c] =
                    make_float2(fmaxf(acc[mt][nt][0] + b0, 0.f),
                                fmaxf(acc[mt][nt][1] + b1, 0.f));
            if (r + 8 < NN)
                *(float2*)&g_h[(size_t)(r + 8) * 64 + c] =
                    make_float2(fmaxf(acc[mt][nt][2] + b0, 0.f),
                                fmaxf(acc[mt][nt][3] + b1, 0.f));
        }
    }
}

// ---------------- GEMM 3: fused GRU -----------------------------------------
__global__ __launch_bounds__(256) void k_mma_gru(const float* __restrict__ h_prev,
                                                 float* __restrict__ out_h) {
    __shared__ __align__(16) float As[128][32];
    __shared__ __align__(16) float Bs[128][32];
    int tid = threadIdx.x;
    int lane = tid & 31, warp = tid >> 5;
    int warpM = warp >> 1, warpN = warp & 1;
    int g = lane >> 2, t = lane & 3;
    int rot = (g & 3) << 3;
    int n0 = blockIdx.x * 128;
    int cb = blockIdx.y * 128;
    float acc[2][8][4] = {};
    for (int kc = 0; kc < 4; kc++) {
        __syncthreads();
        for (int i = tid; i < 4096; i += 256) {
            int m = i >> 5, kk = i & 31;
            int n = n0 + m;
            int kg = kc * 32 + kk;
            float v = 0.f;
            if (n < NN)
                v = (kg < 64) ? g_h[(size_t)n * 64 + kg]
                              : h_prev[(size_t)n * 64 + kg - 64];
            As[m][swz(kk, m)] = to_tf32(v);
        }
        const float4* src = (const float4*)&g_Bgru[(kc * 256 + cb) * 32];
        float4* dst = (float4*)&Bs[0][0];
        for (int i = tid; i < 1024; i += 256) dst[i] = src[i];
        __syncthreads();
#pragma unroll
        for (int s = 0; s < 4; s++) {
            int pc = (s * 8 + 2 * t + rot) & 31;
            uint32_t a[2][4];
#pragma unroll
            for (int mt = 0; mt < 2; mt++) {
                int r = warpM * 32 + mt * 16 + g;
                float2 lo = *(const float2*)&As[r][pc];
                float2 hi = *(const float2*)&As[r + 8][pc];
                a[mt][0] = __float_as_uint(lo.x); a[mt][1] = __float_as_uint(hi.x);
                a[mt][2] = __float_as_uint(lo.y); a[mt][3] = __float_as_uint(hi.y);
            }
#pragma unroll
            for (int nt = 0; nt < 8; nt++) {
                int c = warpN * 64 + nt * 8 + g;
                float2 b = *(const float2*)&Bs[c][pc];
                uint32_t b0 = __float_as_uint(b.x), b1 = __float_as_uint(b.y);
                mma_tf32(acc[0][nt], a[0], b0, b1);
                mma_tf32(acc[1][nt], a[1], b0, b1);
            }
        }
    }
#pragma unroll
    for (int mt = 0; mt < 2; mt++) {
#pragma unroll
        for (int nt = 0; nt < 8; nt++) {
            int cg0 = cb + warpN * 64 + nt * 8;
            int j = (cg0 >> 2) + (t >> 1);
            bool even = (t & 1) == 0;
            float br = g_bias[j], bz = g_bias[64 + j];
            float bn = g_bias[128 + j], bh = g_bias[192 + j];
#pragma unroll
            for (int rh = 0; rh < 2; rh++) {
                int n = n0 + warpM * 32 + mt * 16 + rh * 8 + g;
                float v0 = acc[mt][nt][rh * 2 + 0];
                float v1 = acc[mt][nt][rh * 2 + 1];
                float o0 = __shfl_xor_sync(0xffffffffu, v0, 1);
                float o1 = __shfl_xor_sync(0xffffffffu, v1, 1);
                if (even && n < NN) {
                    float r_ = sigf(v0 + br);
                    float z_ = sigf(v1 + bz);
                    float nv = tanh_fast((o0 + bn) + r_ * (o1 + bh));
                    float hp = h_prev[(size_t)n * 64 + j];
                    out_h[(size_t)n * 64 + j] = (1.f - z_) * nv + z_ * hp;
                }
            }
        }
    }
}

// ---------------- out = (h_next @ W_ro + b_ro)[:, :3] -----------------------
__global__ void k_out(const float* __restrict__ hn, const float* __restrict__ Wro,
                      const float* __restrict__ bro, float* __restrict__ out3) {
    __shared__ float Hs[128][65];
    int n0 = blockIdx.x * 128;
    int tid = threadIdx.x;
    for (int i = tid; i < 128 * 64; i += 128) {
        int nl = i >> 6, k = i & 63;
        int n = n0 + nl;
        Hs[nl][k] = (n < NN) ? hn[(size_t)n * 64 + k] : 0.f;
    }
    __syncthreads();
    int n = n0 + tid;
    if (n < NN) {
        float a0 = bro[0], a1 = bro[1], a2 = bro[2];
#pragma unroll 8
        for (int k = 0; k < 64; k++) {
            float h = Hs[tid][k];
            a0 += h * __ldg(&Wro[k * 64 + 0]);
            a1 += h * __ldg(&Wro[k * 64 + 1]);
            a2 += h * __ldg(&Wro[k * 64 + 2]);
        }
        out3[n * 3 + 0] = a0;
        out3[n * 3 + 1] = a1;
        out3[n * 3 + 2] = a2;
    }
}

// ---------------- launch -----------------------------------------------------
extern "C" void kernel_launch(void* const* d_in, const int* in_sizes, int n_in,
                              void* d_out, int out_size) {
    const float* x       = (const float*)d_in[0];
    const float* h_prev  = (const float*)d_in[1];
    const int* node_idx  = (const int*)d_in[2];
    const int* hedge_idx = (const int*)d_in[3];
    const int* edge_attr = (const int*)d_in[4];
    const float* W_conv  = (const float*)d_in[5];
    const float* b_conv  = (const float*)d_in[6];
    const float* W_mix   = (const float*)d_in[7];
    const float* b_mix   = (const float*)d_in[8];
    const float* W_ih    = (const float*)d_in[9];
    const float* W_hh    = (const float*)d_in[10];
    const float* b_ih    = (const float*)d_in[11];
    const float* b_hh    = (const float*)d_in[12];
    const float* W_ro    = (const float*)d_in[13];
    const float* b_ro    = (const float*)d_in[14];

    float* h_next = (float*)d_out;
    float* out3   = (float*)d_out + (size_t)NN * 64;

    k_zero_cnt<<<(NKB + 255) / 256, 256>>>();
    k_prep<<<194, 256>>>(W_conv, W_mix, b_mix, b_conv, W_ih, W_hh, b_ih, b_hh);
    k_hist<<<(NE + 255) / 256, 256>>>(node_idx, hedge_idx, edge_attr);
    k_scan<<<2, 1024>>>();
    k_perm<<<(NE + 255) / 256, 256>>>(node_idx, hedge_idx, edge_attr);
    k_mma_xl<<<(NN + 127) / 128, 256>>>(x);
    k_gatherA<<<(NKA * 32 + 255) / 256, 256>>>();
    k_gatherB<<<(NKB * 32 + 255) / 256, 256>>>();
    k_mma_mix<<<(NN + 127) / 128, 256>>>();
    k_mma_gru<<<dim3((NN + 127) / 128, 2), 256>>>(h_prev, h_next);
    k_out<<<(NN + 127) / 128, 128>>>(h_next, W_ro, b_ro, out3);
}

// round 4
// speedup vs baseline: 1.7375x; 1.7375x over previous
#include <cuda_runtime.h>
#include <cstdint>

#define NN 100000
#define NH 20000
#define NE 800000
#define NKA (NH*2)     // hedge-type keys
#define NKB (NN*2)     // node-type keys
#define NBA ((NKA + 1023) / 1024)   // 40 offset blocks for A
#define NBB ((NKB + 1023) / 1024)   // 196 offset blocks for B

// ---------------- static device buffers ------------------------------------
__device__ __align__(16) float g_ef[(size_t)NH*128];
__device__ __align__(16) float g_no[(size_t)NN*128];
__device__ __align__(16) float g_xl[(size_t)NN*128];
__device__ __align__(16) float g_h[(size_t)NN*64];
__device__ int g_cntA[NKA], g_offA[NKA], g_curA[NKA];
__device__ int g_cntB[NKB], g_offB[NKB], g_curB[NKB];
__device__ int g_baseA, g_baseB;
__device__ int g_sortA[NE];   // node ids, sorted by (hedge,type)
__device__ int g_sortB[NE];   // ef row offsets, sorted by (node,type)
// Pre-swizzled tf32 B-images
__device__ __align__(16) float g_Bxl[2*128*32];
__device__ __align__(16) float g_Bmix[4*64*32];
__device__ __align__(16) float g_Bgru[4*256*32];
__device__ float g_bias[256];
__device__ float g_bcmix[64];

// ---------------- helpers ---------------------------------------------------
__device__ __forceinline__ float to_tf32(float v) {
    uint32_t u; asm("cvt.rna.tf32.f32 %0, %1;" : "=r"(u) : "f"(v));
    return __uint_as_float(u);
}
__device__ __forceinline__ int swz(int kk, int row) {
    int r = kk & 7;
    int pos = (r < 4) ? (r * 2) : ((r - 4) * 2 + 1);
    int sc = (kk & 24) + pos;
    return (sc + ((row & 3) << 3)) & 31;
}
__device__ __forceinline__ void mma_tf32(float* c, const uint32_t* a,
                                         uint32_t b0, uint32_t b1) {
    asm volatile(
        "mma.sync.aligned.m16n8k8.row.col.f32.tf32.tf32.f32 "
        "{%0,%1,%2,%3}, {%4,%5,%6,%7}, {%8,%9}, {%0,%1,%2,%3};"
        : "+f"(c[0]), "+f"(c[1]), "+f"(c[2]), "+f"(c[3])
        : "r"(a[0]), "r"(a[1]), "r"(a[2]), "r"(a[3]), "r"(b0), "r"(b1));
}
__device__ __forceinline__ float sigf(float x) { return 1.f / (1.f + __expf(-x)); }
__device__ __forceinline__ float tanh_fast(float x) {
    return 1.f - 2.f / (__expf(2.f * x) + 1.f);
}

// ---------------- zero counters ---------------------------------------------
__global__ void k_zero_cnt() {
    int i = blockIdx.x * 256 + threadIdx.x;
    if (i < NKA) g_cntA[i] = 0;
    if (i < NKB) g_cntB[i] = 0;
    if (i == 0) { g_baseA = 0; g_baseB = 0; }
}

// ---------------- histogram -------------------------------------------------
__global__ void k_hist(const int* __restrict__ ni, const int* __restrict__ hi,
                       const int* __restrict__ ea) {
    int e = blockIdx.x * 256 + threadIdx.x;
    if (e >= NE) return;
    int t = ea[e];
    atomicAdd(&g_cntA[hi[e] * 2 + t], 1);
    atomicAdd(&g_cntB[ni[e] * 2 + t], 1);
}

// ---------------- parallel offsets: block scan + atomic range claim ---------
// Segment placement is atomic-order dependent, but segment contents/sums are
// placement-invariant, so results are unaffected.
__global__ __launch_bounds__(1024) void k_offsets() {
    __shared__ int sm[1024];
    __shared__ int blockBase;
    int b = blockIdx.x;
    const int* cnt; int* off; int* cur; int n; int* gbase;
    if (b < NBA) { cnt = g_cntA; off = g_offA; cur = g_curA; n = NKA; gbase = &g_baseA; }
    else { b -= NBA; cnt = g_cntB; off = g_offB; cur = g_curB; n = NKB; gbase = &g_baseB; }
    int tid = threadIdx.x;
    int i = b * 1024 + tid;
    int v = (i < n) ? cnt[i] : 0;
    sm[tid] = v;
    __syncthreads();
    for (int d = 1; d < 1024; d <<= 1) {
        int t = (tid >= d) ? sm[tid - d] : 0;
        __syncthreads();
        sm[tid] += t;
        __syncthreads();
    }
    if (tid == 1023) blockBase = atomicAdd(gbase, sm[1023]);
    __syncthreads();
    if (i < n) {
        int o = blockBase + sm[tid] - v;
        off[i] = o; cur[i] = o;
    }
}

// ---------------- permute: build both sorted lists --------------------------
__global__ void k_perm(const int* __restrict__ ni, const int* __restrict__ hi,
                       const int* __restrict__ ea) {
    int e = blockIdx.x * 256 + threadIdx.x;
    if (e >= NE) return;
    int n = ni[e], h = hi[e], t = ea[e];
    int pA = atomicAdd(&g_curA[h * 2 + t], 1);
    g_sortA[pA] = n;
    int pB = atomicAdd(&g_curB[n * 2 + t], 1);
    g_sortB[pB] = h * 128 + t * 64;
}

// ---------------- prep: swizzled tf32 B-images + biases ---------------------
__global__ void k_prep(const float* __restrict__ Wc, const float* __restrict__ Wmix,
                       const float* __restrict__ bmix, const float* __restrict__ bconv,
                       const float* __restrict__ Wih, const float* __restrict__ Whh,
                       const float* __restrict__ bih, const float* __restrict__ bhh) {
    int idx = blockIdx.x * blockDim.x + threadIdx.x;
    if (idx < 8192) {                     // Bxl: [2][128][32]
        int kc = idx >> 12, rem = idx & 4095, c = rem >> 5, kk = rem & 31;
        int k = kc * 32 + kk;
        int t = c >> 6, j = c & 63;
        g_Bxl[(kc * 128 + c) * 32 + swz(kk, c)] = to_tf32(Wc[t * 4096 + k * 64 + j]);
    } else if (idx < 16384) {             // Bmix: [4][64][32]
        int i = idx - 8192;
        int kc = i >> 11, rem = i & 2047, c = rem >> 5, kk = rem & 31;
        int k = kc * 32 + kk;
        g_Bmix[(kc * 64 + c) * 32 + swz(kk, c)] = to_tf32(Wmix[k * 64 + c]);
    } else if (idx < 49152) {             // Bgru: [4][256][32], c = j*4+seg
        int i = idx - 16384;
        int kc = i >> 13, rem = i & 8191, c = rem >> 5, kk = rem & 31;
        int k = kc * 32 + kk;
        int j = c >> 2, seg = c & 3;
        float v = 0.f;
        if (k < 64) {
            if (seg == 0)      v = Wih[k * 192 + j];
            else if (seg == 1) v = Wih[k * 192 + 64 + j];
            else if (seg == 2) v = Wih[k * 192 + 128 + j];
        } else {
            int k2 = k - 64;
            if (seg == 0)      v = Whh[k2 * 192 + j];
            else if (seg == 1) v = Whh[k2 * 192 + 64 + j];
            else if (seg == 3) v = Whh[k2 * 192 + 128 + j];
        }
        g_Bgru[(kc * 256 + c) * 32 + swz(kk, c)] = to_tf32(v);
    } else if (idx < 49152 + 256) {       // GRU bias (seg-major)
        int c = idx - 49152;
        int seg = c >> 6, j = c & 63;
        float b;
        if (seg == 0)      b = bih[j] + bhh[j];
        else if (seg == 1) b = bih[64 + j] + bhh[64 + j];
        else if (seg == 2) b = bih[128 + j];
        else               b = bhh[128 + j];
        g_bias[c] = b;
    } else if (idx < 49152 + 256 + 64) {  // folded mix bias
        int j = idx - 49152 - 256;
        float s = bmix[j];
        for (int k = 0; k < 128; k++) s += bconv[k] * Wmix[k * 64 + j];
        g_bcmix[j] = s;
    }
}

// ---------------- GEMM 1: xl = x @ [Wc0|Wc1] --------------------------------
__global__ __launch_bounds__(256) void k_mma_xl(const float* __restrict__ x) {
    __shared__ __align__(16) float As[128][32];
    __shared__ __align__(16) float Bs[128][32];
    int tid = threadIdx.x;
    int lane = tid & 31, warp = tid >> 5;
    int warpM = warp >> 1, warpN = warp & 1;
    int g = lane >> 2, t = lane & 3;
    int rot = (g & 3) << 3;
    int n0 = blockIdx.x * 128;
    float acc[2][8][4] = {};
    for (int kc = 0; kc < 2; kc++) {
        __syncthreads();
        for (int i = tid; i < 4096; i += 256) {
            int m = i >> 5, kk = i & 31;
            int n = n0 + m;
            float v = (n < NN) ? x[(size_t)n * 64 + kc * 32 + kk] : 0.f;
            As[m][swz(kk, m)] = to_tf32(v);
        }
        const float4* src = (const float4*)&g_Bxl[kc * 4096];
        float4* dst = (float4*)&Bs[0][0];
        for (int i = tid; i < 1024; i += 256) dst[i] = src[i];
        __syncthreads();
#pragma unroll
        for (int s = 0; s < 4; s++) {
            int pc = (s * 8 + 2 * t + rot) & 31;
            uint32_t a[2][4];
#pragma unroll
            for (int mt = 0; mt < 2; mt++) {
                int r = warpM * 32 + mt * 16 + g;
                float2 lo = *(const float2*)&As[r][pc];
                float2 hi = *(const float2*)&As[r + 8][pc];
                a[mt][0] = __float_as_uint(lo.x); a[mt][1] = __float_as_uint(hi.x);
                a[mt][2] = __float_as_uint(lo.y); a[mt][3] = __float_as_uint(hi.y);
            }
#pragma unroll
            for (int nt = 0; nt < 8; nt++) {
                int c = warpN * 64 + nt * 8 + g;
                float2 b = *(const float2*)&Bs[c][pc];
                uint32_t b0 = __float_as_uint(b.x), b1 = __float_as_uint(b.y);
                mma_tf32(acc[0][nt], a[0], b0, b1);
                mma_tf32(acc[1][nt], a[1], b0, b1);
            }
        }
    }
#pragma unroll
    for (int mt = 0; mt < 2; mt++) {
        int r = n0 + warpM * 32 + mt * 16 + g;
#pragma unroll
        for (int nt = 0; nt < 8; nt++) {
            int c = warpN * 64 + nt * 8 + 2 * t;
            if (r < NN)
                *(float2*)&g_xl[(size_t)r * 128 + c] =
                    make_float2(acc[mt][nt][0], acc[mt][nt][1]);
            if (r + 8 < NN)
                *(float2*)&g_xl[(size_t)(r + 8) * 128 + c] =
                    make_float2(acc[mt][nt][2], acc[mt][nt][3]);
        }
    }
}

// ---------------- gather A: ef[h,t] = Binv * sum xl[node,t] ------------------
__global__ __launch_bounds__(256) void k_gatherA() {
    int key = (blockIdx.x * 256 + threadIdx.x) >> 5;
    if (key >= NKA) return;
    int lane = threadIdx.x & 31;
    int t = key & 1, h = key >> 1;
    int base = g_offA[key], cnt = g_cntA[key];
    const float* xb = g_xl + t * 64 + lane * 2;
    float ax = 0.f, ay = 0.f;
    int i = 0;
    for (; i + 4 <= cnt; i += 4) {
        int n0 = g_sortA[base + i + 0];
        int n1 = g_sortA[base + i + 1];
        int n2 = g_sortA[base + i + 2];
        int n3 = g_sortA[base + i + 3];
        float2 v0 = *(const float2*)(xb + (size_t)n0 * 128);
        float2 v1 = *(const float2*)(xb + (size_t)n1 * 128);
        float2 v2 = *(const float2*)(xb + (size_t)n2 * 128);
        float2 v3 = *(const float2*)(xb + (size_t)n3 * 128);
        ax += (v0.x + v1.x) + (v2.x + v3.x);
        ay += (v0.y + v1.y) + (v2.y + v3.y);
    }
    for (; i < cnt; i++) {
        int n = g_sortA[base + i];
        float2 v = *(const float2*)(xb + (size_t)n * 128);
        ax += v.x; ay += v.y;
    }
    float s = (cnt > 0) ? 1.f / (float)cnt : 0.f;
    *(float2*)&g_ef[(size_t)h * 128 + t * 64 + lane * 2] = make_float2(ax * s, ay * s);
}

// ---------------- gather B: no[n,t] = Dinv * sum ef[h,t] ---------------------
__global__ __launch_bounds__(256) void k_gatherB() {
    int key = (blockIdx.x * 256 + threadIdx.x) >> 5;
    if (key >= NKB) return;
    int lane = threadIdx.x & 31;
    int t = key & 1, n = key >> 1;
    int base = g_offB[key], cnt = g_cntB[key];
    const float* eb = g_ef + lane * 2;
    float ax = 0.f, ay = 0.f;
    int i = 0;
    for (; i + 4 <= cnt; i += 4) {
        int o0 = g_sortB[base + i + 0];
        int o1 = g_sortB[base + i + 1];
        int o2 = g_sortB[base + i + 2];
        int o3 = g_sortB[base + i + 3];
        float2 v0 = *(const float2*)(eb + o0);
        float2 v1 = *(const float2*)(eb + o1);
        float2 v2 = *(const float2*)(eb + o2);
        float2 v3 = *(const float2*)(eb + o3);
        ax += (v0.x + v1.x) + (v2.x + v3.x);
        ay += (v0.y + v1.y) + (v2.y + v3.y);
    }
    for (; i < cnt; i++) {
        int o = g_sortB[base + i];
        float2 v = *(const float2*)(eb + o);
        ax += v.x; ay += v.y;
    }
    float s = (cnt > 0) ? 1.f / (float)cnt : 0.f;
    *(float2*)&g_no[(size_t)n * 128 + t * 64 + lane * 2] = make_float2(ax * s, ay * s);
}

// ---------------- GEMM 2: h = relu(no @ Wmix + bcmix) -----------------------
__global__ __launch_bounds__(256) void k_mma_mix() {
    __shared__ __align__(16) float As[128][32];
    __shared__ __align__(16) float Bs[64][32];
    int tid = threadIdx.x;
    int lane = tid & 31, warp = tid >> 5;
    int warpM = warp >> 1, warpN = warp & 1;
    int g = lane >> 2, t = lane & 3;
    int rot = (g & 3) << 3;
    int n0 = blockIdx.x * 128;
    float acc[2][4][4] = {};
    for (int kc = 0; kc < 4; kc++) {
        __syncthreads();
        for (int i = tid; i < 4096; i += 256) {
            int m = i >> 5, kk = i & 31;
            int n = n0 + m;
            float v = (n < NN) ? g_no[(size_t)n * 128 + kc * 32 + kk] : 0.f;
            As[m][swz(kk, m)] = to_tf32(v);
        }
        const float4* src = (const float4*)&g_Bmix[kc * 2048];
        float4* dst = (float4*)&Bs[0][0];
        for (int i = tid; i < 512; i += 256) dst[i] = src[i];
        __syncthreads();
#pragma unroll
        for (int s = 0; s < 4; s++) {
            int pc = (s * 8 + 2 * t + rot) & 31;
            uint32_t a[2][4];
#pragma unroll
            for (int mt = 0; mt < 2; mt++) {
                int r = warpM * 32 + mt * 16 + g;
                float2 lo = *(const float2*)&As[r][pc];
                float2 hi = *(const float2*)&As[r + 8][pc];
                a[mt][0] = __float_as_uint(lo.x); a[mt][1] = __float_as_uint(hi.x);
                a[mt][2] = __float_as_uint(lo.y); a[mt][3] = __float_as_uint(hi.y);
            }
#pragma unroll
            for (int nt = 0; nt < 4; nt++) {
                int c = warpN * 32 + nt * 8 + g;
                float2 b = *(const float2*)&Bs[c][pc];
                uint32_t b0 = __float_as_uint(b.x), b1 = __float_as_uint(b.y);
                mma_tf32(acc[0][nt], a[0], b0, b1);
                mma_tf32(acc[1][nt], a[1], b0, b1);
            }
        }
    }
#pragma unroll
    for (int mt = 0; mt < 2; mt++) {
        int r = n0 + warpM * 32 + mt * 16 + g;
#pragma unroll
        for (int nt = 0; nt < 4; nt++) {
            int c = warpN * 32 + nt * 8 + 2 * t;
            float b0 = g_bcmix[c], b1 = g_bcmix[c + 1];
            if (r < NN)
                *(float2*)&g_h[(size_t)r * 64 + c] =
                    make_float2(fmaxf(acc[mt][nt][0] + b0, 0.f),
                                fmaxf(acc[mt][nt][1] + b1, 0.f));
            if (r + 8 < NN)
                *(float2*)&g_h[(size_t)(r + 8) * 64 + c] =
                    make_float2(fmaxf(acc[mt][nt][2] + b0, 0.f),
                                fmaxf(acc[mt][nt][3] + b1, 0.f));
        }
    }
}

// ---------------- GEMM 3: fused GRU -----------------------------------------
__global__ __launch_bounds__(256) void k_mma_gru(const float* __restrict__ h_prev,
                                                 float* __restrict__ out_h) {
    __shared__ __align__(16) float As[128][32];
    __shared__ __align__(16) float Bs[128][32];
    int tid = threadIdx.x;
    int lane = tid & 31, warp = tid >> 5;
    int warpM = warp >> 1, warpN = warp & 1;
    int g = lane >> 2, t = lane & 3;
    int rot = (g & 3) << 3;
    int n0 = blockIdx.x * 128;
    int cb = blockIdx.y * 128;
    float acc[2][8][4] = {};
    for (int kc = 0; kc < 4; kc++) {
        __syncthreads();
        for (int i = tid; i < 4096; i += 256) {
            int m = i >> 5, kk = i & 31;
            int n = n0 + m;
            int kg = kc * 32 + kk;
            float v = 0.f;
            if (n < NN)
                v = (kg < 64) ? g_h[(size_t)n * 64 + kg]
                              : h_prev[(size_t)n * 64 + kg - 64];
            As[m][swz(kk, m)] = to_tf32(v);
        }
        const float4* src = (const float4*)&g_Bgru[(kc * 256 + cb) * 32];
        float4* dst = (float4*)&Bs[0][0];
        for (int i = tid; i < 1024; i += 256) dst[i] = src[i];
        __syncthreads();
#pragma unroll
        for (int s = 0; s < 4; s++) {
            int pc = (s * 8 + 2 * t + rot) & 31;
            uint32_t a[2][4];
#pragma unroll
            for (int mt = 0; mt < 2; mt++) {
                int r = warpM * 32 + mt * 16 + g;
                float2 lo = *(const float2*)&As[r][pc];
                float2 hi = *(const float2*)&As[r + 8][pc];
                a[mt][0] = __float_as_uint(lo.x); a[mt][1] = __float_as_uint(hi.x);
                a[mt][2] = __float_as_uint(lo.y); a[mt][3] = __float_as_uint(hi.y);
            }
#pragma unroll
            for (int nt = 0; nt < 8; nt++) {
                int c = warpN * 64 + nt * 8 + g;
                float2 b = *(const float2*)&Bs[c][pc];
                uint32_t b0 = __float_as_uint(b.x), b1 = __float_as_uint(b.y);
                mma_tf32(acc[0][nt], a[0], b0, b1);
                mma_tf32(acc[1][nt], a[1], b0, b1);
            }
        }
    }
#pragma unroll
    for (int mt = 0; mt < 2; mt++) {
#pragma unroll
        for (int nt = 0; nt < 8; nt++) {
            int cg0 = cb + warpN * 64 + nt * 8;
            int j = (cg0 >> 2) + (t >> 1);
            bool even = (t & 1) == 0;
            float br = g_bias[j], bz = g_bias[64 + j];
            float bn = g_bias[128 + j], bh = g_bias[192 + j];
#pragma unroll
            for (int rh = 0; rh < 2; rh++) {
                int n = n0 + warpM * 32 + mt * 16 + rh * 8 + g;
                float v0 = acc[mt][nt][rh * 2 + 0];
                float v1 = acc[mt][nt][rh * 2 + 1];
                float o0 = __shfl_xor_sync(0xffffffffu, v0, 1);
                float o1 = __shfl_xor_sync(0xffffffffu, v1, 1);
                if (even && n < NN) {
                    float r_ = sigf(v0 + br);
                    float z_ = sigf(v1 + bz);
                    float nv = tanh_fast((o0 + bn) + r_ * (o1 + bh));
                    float hp = h_prev[(size_t)n * 64 + j];
                    out_h[(size_t)n * 64 + j] = (1.f - z_) * nv + z_ * hp;
                }
            }
        }
    }
}

// ---------------- out = (h_next @ W_ro + b_ro)[:, :3] -----------------------
__global__ void k_out(const float* __restrict__ hn, const float* __restrict__ Wro,
                      const float* __restrict__ bro, float* __restrict__ out3) {
    __shared__ float Hs[128][65];
    int n0 = blockIdx.x * 128;
    int tid = threadIdx.x;
    for (int i = tid; i < 128 * 64; i += 128) {
        int nl = i >> 6, k = i & 63;
        int n = n0 + nl;
        Hs[nl][k] = (n < NN) ? hn[(size_t)n * 64 + k] : 0.f;
    }
    __syncthreads();
    int n = n0 + tid;
    if (n < NN) {
        float a0 = bro[0], a1 = bro[1], a2 = bro[2];
#pragma unroll 8
        for (int k = 0; k < 64; k++) {
            float h = Hs[tid][k];
            a0 += h * __ldg(&Wro[k * 64 + 0]);
            a1 += h * __ldg(&Wro[k * 64 + 1]);
            a2 += h * __ldg(&Wro[k * 64 + 2]);
        }
        out3[n * 3 + 0] = a0;
        out3[n * 3 + 1] = a1;
        out3[n * 3 + 2] = a2;
    }
}

// ---------------- launch -----------------------------------------------------
extern "C" void kernel_launch(void* const* d_in, const int* in_sizes, int n_in,
                              void* d_out, int out_size) {
    const float* x       = (const float*)d_in[0];
    const float* h_prev  = (const float*)d_in[1];
    const int* node_idx  = (const int*)d_in[2];
    const int* hedge_idx = (const int*)d_in[3];
    const int* edge_attr = (const int*)d_in[4];
    const float* W_conv  = (const float*)d_in[5];
    const float* b_conv  = (const float*)d_in[6];
    const float* W_mix   = (const float*)d_in[7];
    const float* b_mix   = (const float*)d_in[8];
    const float* W_ih    = (const float*)d_in[9];
    const float* W_hh    = (const float*)d_in[10];
    const float* b_ih    = (const float*)d_in[11];
    const float* b_hh    = (const float*)d_in[12];
    const float* W_ro    = (const float*)d_in[13];
    const float* b_ro    = (const float*)d_in[14];

    float* h_next = (float*)d_out;
    float* out3   = (float*)d_out + (size_t)NN * 64;

    k_zero_cnt<<<(NKB + 255) / 256, 256>>>();
    k_prep<<<194, 256>>>(W_conv, W_mix, b_mix, b_conv, W_ih, W_hh, b_ih, b_hh);
    k_hist<<<(NE + 255) / 256, 256>>>(node_idx, hedge_idx, edge_attr);
    k_offsets<<<NBA + NBB, 1024>>>();
    k_perm<<<(NE + 255) / 256, 256>>>(node_idx, hedge_idx, edge_attr);
    k_mma_xl<<<(NN + 127) / 128, 256>>>(x);
    k_gatherA<<<(NKA * 32 + 255) / 256, 256>>>();
    k_gatherB<<<(NKB * 32 + 255) / 256, 256>>>();
    k_mma_mix<<<(NN + 127) / 128, 256>>>();
    k_mma_gru<<<dim3((NN + 127) / 128, 2), 256>>>(h_prev, h_next);
    k_out<<<(NN + 127) / 128, 128>>>(h_next, W_ro, b_ro, out3);
}

// round 5
// speedup vs baseline: 2.3582x; 1.3572x over previous
#include <cuda_runtime.h>
#include <cstdint>

#define NN 100000
#define NH 20000
#define NE 800000
#define NKA (NH*2)     // hedge-type keys
#define NKB (NN*2)     // node-type keys
#define NBA ((NKA + 1023) / 1024)
#define NBB ((NKB + 1023) / 1024)

// ---------------- static device buffers ------------------------------------
__device__ __align__(16) float g_aggA[(size_t)2*NH*64];  // (Σx)/cnt per (t,h)
__device__ __align__(16) float g_efm[(size_t)2*NH*64];   // aggA @ Wcomb_t
__device__ __align__(16) float g_h[(size_t)NN*64];       // relu(mix)
__device__ int g_cntA[NKA], g_offA[NKA], g_curA[NKA];
__device__ int g_cntB[NKB], g_offB[NKB], g_curB[NKB];
__device__ int g_baseA, g_baseB;
__device__ int g_sortA[NE];   // node ids, sorted by (hedge,type)
__device__ int g_sortB[NE];   // efm row offsets (floats), sorted by (node,type)
// Pre-swizzled tf32 B-images
__device__ __align__(16) float g_Bef[2*2*64*32];   // Wcomb_t images
__device__ __align__(16) float g_Bgru[4*256*32];
__device__ float g_bias[256];
__device__ float g_bcmix[64];

// ---------------- helpers ---------------------------------------------------
__device__ __forceinline__ float to_tf32(float v) {
    uint32_t u; asm("cvt.rna.tf32.f32 %0, %1;" : "=r"(u) : "f"(v));
    return __uint_as_float(u);
}
__device__ __forceinline__ int swz(int kk, int row) {
    int r = kk & 7;
    int pos = (r < 4) ? (r * 2) : ((r - 4) * 2 + 1);
    int sc = (kk & 24) + pos;
    return (sc + ((row & 3) << 3)) & 31;
}
__device__ __forceinline__ void mma_tf32(float* c, const uint32_t* a,
                                         uint32_t b0, uint32_t b1) {
    asm volatile(
        "mma.sync.aligned.m16n8k8.row.col.f32.tf32.tf32.f32 "
        "{%0,%1,%2,%3}, {%4,%5,%6,%7}, {%8,%9}, {%0,%1,%2,%3};"
        : "+f"(c[0]), "+f"(c[1]), "+f"(c[2]), "+f"(c[3])
        : "r"(a[0]), "r"(a[1]), "r"(a[2]), "r"(a[3]), "r"(b0), "r"(b1));
}
__device__ __forceinline__ float sigf(float x) { return 1.f / (1.f + __expf(-x)); }
__device__ __forceinline__ float tanh_fast(float x) {
    return 1.f - 2.f / (__expf(2.f * x) + 1.f);
}

// ---------------- zero counters ---------------------------------------------
__global__ void k_zero_cnt() {
    int i = blockIdx.x * 256 + threadIdx.x;
    if (i < NKA) g_cntA[i] = 0;
    if (i < NKB) g_cntB[i] = 0;
    if (i == 0) { g_baseA = 0; g_baseB = 0; }
}

// ---------------- histogram -------------------------------------------------
__global__ void k_hist(const int* __restrict__ ni, const int* __restrict__ hi,
                       const int* __restrict__ ea) {
    int e = blockIdx.x * 256 + threadIdx.x;
    if (e >= NE) return;
    int t = ea[e];
    atomicAdd(&g_cntA[hi[e] * 2 + t], 1);
    atomicAdd(&g_cntB[ni[e] * 2 + t], 1);
}

// ---------------- parallel offsets: block scan + atomic range claim ---------
__global__ __launch_bounds__(1024) void k_offsets() {
    __shared__ int sm[1024];
    __shared__ int blockBase;
    int b = blockIdx.x;
    const int* cnt; int* off; int* cur; int n; int* gbase;
    if (b < NBA) { cnt = g_cntA; off = g_offA; cur = g_curA; n = NKA; gbase = &g_baseA; }
    else { b -= NBA; cnt = g_cntB; off = g_offB; cur = g_curB; n = NKB; gbase = &g_baseB; }
    int tid = threadIdx.x;
    int i = b * 1024 + tid;
    int v = (i < n) ? cnt[i] : 0;
    sm[tid] = v;
    __syncthreads();
    for (int d = 1; d < 1024; d <<= 1) {
        int t = (tid >= d) ? sm[tid - d] : 0;
        __syncthreads();
        sm[tid] += t;
        __syncthreads();
    }
    if (tid == 1023) blockBase = atomicAdd(gbase, sm[1023]);
    __syncthreads();
    if (i < n) {
        int o = blockBase + sm[tid] - v;
        off[i] = o; cur[i] = o;
    }
}

// ---------------- permute: build both sorted lists --------------------------
__global__ void k_perm(const int* __restrict__ ni, const int* __restrict__ hi,
                       const int* __restrict__ ea) {
    int e = blockIdx.x * 256 + threadIdx.x;
    if (e >= NE) return;
    int n = ni[e], h = hi[e], t = ea[e];
    int pA = atomicAdd(&g_curA[h * 2 + t], 1);
    g_sortA[pA] = n;
    int pB = atomicAdd(&g_curB[n * 2 + t], 1);
    g_sortB[pB] = (t * NH + h) * 64;
}

// ---------------- prep: swizzled tf32 B-images + biases ---------------------
// Wcomb_t[i][j] = sum_m Wconv[t][i][m] * Wmix[(t*64+m)][j]  (computed inline)
__global__ void k_prep(const float* __restrict__ Wc, const float* __restrict__ Wmix,
                       const float* __restrict__ bmix, const float* __restrict__ bconv,
                       const float* __restrict__ Wih, const float* __restrict__ Whh,
                       const float* __restrict__ bih, const float* __restrict__ bhh) {
    int idx = blockIdx.x * blockDim.x + threadIdx.x;
    if (idx < 8192) {                     // Bef: [2][2 kc][64 c][32]
        int t = idx >> 12, rem = idx & 4095;
        int kc = rem >> 11, rem2 = rem & 2047, c = rem2 >> 5, kk = rem2 & 31;
        int k = kc * 32 + kk;             // input-dim index
        float s = 0.f;
        const float* wr = Wc + t * 4096 + k * 64;
        const float* wm = Wmix + (size_t)t * 64 * 64 + c;
#pragma unroll 8
        for (int m = 0; m < 64; m++) s += wr[m] * wm[(size_t)m * 64];
        g_Bef[((t * 2 + kc) * 64 + c) * 32 + swz(kk, c)] = to_tf32(s);
    } else if (idx < 40960) {             // Bgru: [4][256][32], c = j*4+seg
        int i = idx - 8192;
        int kc = i >> 13, rem = i & 8191, c = rem >> 5, kk = rem & 31;
        int k = kc * 32 + kk;
        int j = c >> 2, seg = c & 3;
        float v = 0.f;
        if (k < 64) {
            if (seg == 0)      v = Wih[k * 192 + j];
            else if (seg == 1) v = Wih[k * 192 + 64 + j];
            else if (seg == 2) v = Wih[k * 192 + 128 + j];
        } else {
            int k2 = k - 64;
            if (seg == 0)      v = Whh[k2 * 192 + j];
            else if (seg == 1) v = Whh[k2 * 192 + 64 + j];
            else if (seg == 3) v = Whh[k2 * 192 + 128 + j];
        }
        g_Bgru[(kc * 256 + c) * 32 + swz(kk, c)] = to_tf32(v);
    } else if (idx < 40960 + 256) {       // GRU bias (seg-major)
        int c = idx - 40960;
        int seg = c >> 6, j = c & 63;
        float b;
        if (seg == 0)      b = bih[j] + bhh[j];
        else if (seg == 1) b = bih[64 + j] + bhh[64 + j];
        else if (seg == 2) b = bih[128 + j];
        else               b = bhh[128 + j];
        g_bias[c] = b;
    } else if (idx < 40960 + 256 + 64) {  // folded mix bias
        int j = idx - 40960 - 256;
        float s = bmix[j];
        for (int k = 0; k < 128; k++) s += bconv[k] * Wmix[k * 64 + j];
        g_bcmix[j] = s;
    }
}

// ---------------- gather A: aggA[t,h] = (1/cnt) * sum x[node] ----------------
__global__ __launch_bounds__(256) void k_gatherA(const float* __restrict__ x) {
    int key = (blockIdx.x * 256 + threadIdx.x) >> 5;
    if (key >= NKA) return;
    int lane = threadIdx.x & 31;
    int t = key & 1, h = key >> 1;
    int base = g_offA[key], cnt = g_cntA[key];
    const float* xb = x + lane * 2;
    float ax = 0.f, ay = 0.f;
    int i = 0;
    for (; i + 4 <= cnt; i += 4) {
        int n0 = g_sortA[base + i + 0];
        int n1 = g_sortA[base + i + 1];
        int n2 = g_sortA[base + i + 2];
        int n3 = g_sortA[base + i + 3];
        float2 v0 = *(const float2*)(xb + (size_t)n0 * 64);
        float2 v1 = *(const float2*)(xb + (size_t)n1 * 64);
        float2 v2 = *(const float2*)(xb + (size_t)n2 * 64);
        float2 v3 = *(const float2*)(xb + (size_t)n3 * 64);
        ax += (v0.x + v1.x) + (v2.x + v3.x);
        ay += (v0.y + v1.y) + (v2.y + v3.y);
    }
    for (; i < cnt; i++) {
        int n = g_sortA[base + i];
        float2 v = *(const float2*)(xb + (size_t)n * 64);
        ax += v.x; ay += v.y;
    }
    float s = (cnt > 0) ? 1.f / (float)cnt : 0.f;
    *(float2*)&g_aggA[((size_t)t * NH + h) * 64 + lane * 2] = make_float2(ax * s, ay * s);
}

// ---------------- GEMM: efm = aggA @ Wcomb_t   (M=NH per type, N=64, K=64) --
__global__ __launch_bounds__(256) void k_mma_ef() {
    __shared__ __align__(16) float As[128][32];
    __shared__ __align__(16) float Bs[64][32];
    int tid = threadIdx.x;
    int lane = tid & 31, warp = tid >> 5;
    int warpM = warp >> 1, warpN = warp & 1;
    int g = lane >> 2, t4 = lane & 3;
    int rot = (g & 3) << 3;
    int n0 = blockIdx.x * 128;
    int ty = blockIdx.y;                 // edge type
    float acc[2][4][4] = {};
    for (int kc = 0; kc < 2; kc++) {
        __syncthreads();
        for (int i = tid; i < 4096; i += 256) {
            int m = i >> 5, kk = i & 31;
            int n = n0 + m;
            float v = (n < NH) ? g_aggA[((size_t)ty * NH + n) * 64 + kc * 32 + kk] : 0.f;
            As[m][swz(kk, m)] = to_tf32(v);
        }
        const float4* src = (const float4*)&g_Bef[(ty * 2 + kc) * 2048];
        float4* dst = (float4*)&Bs[0][0];
        for (int i = tid; i < 512; i += 256) dst[i] = src[i];
        __syncthreads();
#pragma unroll
        for (int s = 0; s < 4; s++) {
            int pc = (s * 8 + 2 * t4 + rot) & 31;
            uint32_t a[2][4];
#pragma unroll
            for (int mt = 0; mt < 2; mt++) {
                int r = warpM * 32 + mt * 16 + g;
                float2 lo = *(const float2*)&As[r][pc];
                float2 hi = *(const float2*)&As[r + 8][pc];
                a[mt][0] = __float_as_uint(lo.x); a[mt][1] = __float_as_uint(hi.x);
                a[mt][2] = __float_as_uint(lo.y); a[mt][3] = __float_as_uint(hi.y);
            }
#pragma unroll
            for (int nt = 0; nt < 4; nt++) {
                int c = warpN * 32 + nt * 8 + g;
                float2 b = *(const float2*)&Bs[c][pc];
                uint32_t b0 = __float_as_uint(b.x), b1 = __float_as_uint(b.y);
                mma_tf32(acc[0][nt], a[0], b0, b1);
                mma_tf32(acc[1][nt], a[1], b0, b1);
            }
        }
    }
#pragma unroll
    for (int mt = 0; mt < 2; mt++) {
        int r = n0 + warpM * 32 + mt * 16 + g;
#pragma unroll
        for (int nt = 0; nt < 4; nt++) {
            int c = warpN * 32 + nt * 8 + 2 * t4;
            if (r < NH)
                *(float2*)&g_efm[((size_t)ty * NH + r) * 64 + c] =
                    make_float2(acc[mt][nt][0], acc[mt][nt][1]);
            if (r + 8 < NH)
                *(float2*)&g_efm[((size_t)ty * NH + r + 8) * 64 + c] =
                    make_float2(acc[mt][nt][2], acc[mt][nt][3]);
        }
    }
}

// ---------------- gather B: h[n] = relu(sum_t Dinv_t * sum efm + bcmix) -----
__global__ __launch_bounds__(256) void k_gatherB() {
    int node = (blockIdx.x * 256 + threadIdx.x) >> 5;
    if (node >= NN) return;
    int lane = threadIdx.x & 31;
    const float* eb = g_efm + lane * 2;
    float ax = 0.f, ay = 0.f;
#pragma unroll
    for (int t = 0; t < 2; t++) {
        int key = node * 2 + t;
        int base = g_offB[key], cnt = g_cntB[key];
        float sx = 0.f, sy = 0.f;
        int i = 0;
        for (; i + 4 <= cnt; i += 4) {
            int o0 = g_sortB[base + i + 0];
            int o1 = g_sortB[base + i + 1];
            int o2 = g_sortB[base + i + 2];
            int o3 = g_sortB[base + i + 3];
            float2 v0 = *(const float2*)(eb + o0);
            float2 v1 = *(const float2*)(eb + o1);
            float2 v2 = *(const float2*)(eb + o2);
            float2 v3 = *(const float2*)(eb + o3);
            sx += (v0.x + v1.x) + (v2.x + v3.x);
            sy += (v0.y + v1.y) + (v2.y + v3.y);
        }
        for (; i < cnt; i++) {
            int o = g_sortB[base + i];
            float2 v = *(const float2*)(eb + o);
            sx += v.x; sy += v.y;
        }
        float s = (cnt > 0) ? 1.f / (float)cnt : 0.f;
        ax += sx * s; ay += sy * s;
    }
    float b0 = g_bcmix[lane * 2], b1 = g_bcmix[lane * 2 + 1];
    *(float2*)&g_h[(size_t)node * 64 + lane * 2] =
        make_float2(fmaxf(ax + b0, 0.f), fmaxf(ay + b1, 0.f));
}

// ---------------- GEMM: fused GRU  [h|h_prev]@Bgru (128x256), epilogue ------
__global__ __launch_bounds__(512) void k_mma_gru(const float* __restrict__ h_prev,
                                                 float* __restrict__ out_h) {
    __shared__ __align__(16) float As[128][32];
    __shared__ __align__(16) float Bs[256][32];
    int tid = threadIdx.x;
    int lane = tid & 31, warp = tid >> 5;
    int warpM = warp >> 2, warpN = warp & 3;
    int g = lane >> 2, t = lane & 3;
    int rot = (g & 3) << 3;
    int n0 = blockIdx.x * 128;
    float acc[2][8][4] = {};
    for (int kc = 0; kc < 4; kc++) {
        __syncthreads();
        for (int i = tid; i < 4096; i += 512) {
            int m = i >> 5, kk = i & 31;
            int n = n0 + m;
            int kg = kc * 32 + kk;
            float v = 0.f;
            if (n < NN)
                v = (kg < 64) ? g_h[(size_t)n * 64 + kg]
                              : h_prev[(size_t)n * 64 + kg - 64];
            As[m][swz(kk, m)] = to_tf32(v);
        }
        const float4* src = (const float4*)&g_Bgru[kc * 8192];
        float4* dst = (float4*)&Bs[0][0];
        for (int i = tid; i < 2048; i += 512) dst[i] = src[i];
        __syncthreads();
#pragma unroll
        for (int s = 0; s < 4; s++) {
            int pc = (s * 8 + 2 * t + rot) & 31;
            uint32_t a[2][4];
#pragma unroll
            for (int mt = 0; mt < 2; mt++) {
                int r = warpM * 32 + mt * 16 + g;
                float2 lo = *(const float2*)&As[r][pc];
                float2 hi = *(const float2*)&As[r + 8][pc];
                a[mt][0] = __float_as_uint(lo.x); a[mt][1] = __float_as_uint(hi.x);
                a[mt][2] = __float_as_uint(lo.y); a[mt][3] = __float_as_uint(hi.y);
            }
#pragma unroll
            for (int nt = 0; nt < 8; nt++) {
                int c = warpN * 64 + nt * 8 + g;
                float2 b = *(const float2*)&Bs[c][pc];
                uint32_t b0 = __float_as_uint(b.x), b1 = __float_as_uint(b.y);
                mma_tf32(acc[0][nt], a[0], b0, b1);
                mma_tf32(acc[1][nt], a[1], b0, b1);
            }
        }
    }
    // gate epilogue: cols interleaved c = j*4+seg; lane pairs exchange halves
#pragma unroll
    for (int mt = 0; mt < 2; mt++) {
#pragma unroll
        for (int nt = 0; nt < 8; nt++) {
            int cg0 = warpN * 64 + nt * 8;
            int j = (cg0 >> 2) + (t >> 1);
            bool even = (t & 1) == 0;
            float br = g_bias[j], bz = g_bias[64 + j];
            float bn = g_bias[128 + j], bh = g_bias[192 + j];
#pragma unroll
            for (int rh = 0; rh < 2; rh++) {
                int n = n0 + warpM * 32 + mt * 16 + rh * 8 + g;
                float v0 = acc[mt][nt][rh * 2 + 0];
                float v1 = acc[mt][nt][rh * 2 + 1];
                float o0 = __shfl_xor_sync(0xffffffffu, v0, 1);
                float o1 = __shfl_xor_sync(0xffffffffu, v1, 1);
                if (even && n < NN) {
                    float r_ = sigf(v0 + br);
                    float z_ = sigf(v1 + bz);
                    float nv = tanh_fast((o0 + bn) + r_ * (o1 + bh));
                    float hp = h_prev[(size_t)n * 64 + j];
                    out_h[(size_t)n * 64 + j] = (1.f - z_) * nv + z_ * hp;
                }
            }
        }
    }
}

// ---------------- out = (h_next @ W_ro + b_ro)[:, :3] -----------------------
__global__ void k_out(const float* __restrict__ hn, const float* __restrict__ Wro,
                      const float* __restrict__ bro, float* __restrict__ out3) {
    __shared__ float Hs[128][65];
    int n0 = blockIdx.x * 128;
    int tid = threadIdx.x;
    for (int i = tid; i < 128 * 64; i += 128) {
        int nl = i >> 6, k = i & 63;
        int n = n0 + nl;
        Hs[nl][k] = (n < NN) ? hn[(size_t)n * 64 + k] : 0.f;
    }
    __syncthreads();
    int n = n0 + tid;
    if (n < NN) {
        float a0 = bro[0], a1 = bro[1], a2 = bro[2];
#pragma unroll 8
        for (int k = 0; k < 64; k++) {
            float h = Hs[tid][k];
            a0 += h * __ldg(&Wro[k * 64 + 0]);
            a1 += h * __ldg(&Wro[k * 64 + 1]);
            a2 += h * __ldg(&Wro[k * 64 + 2]);
        }
        out3[n * 3 + 0] = a0;
        out3[n * 3 + 1] = a1;
        out3[n * 3 + 2] = a2;
    }
}

// ---------------- launch -----------------------------------------------------
extern "C" void kernel_launch(void* const* d_in, const int* in_sizes, int n_in,
                              void* d_out, int out_size) {
    const float* x       = (const float*)d_in[0];
    const float* h_prev  = (const float*)d_in[1];
    const int* node_idx  = (const int*)d_in[2];
    const int* hedge_idx = (const int*)d_in[3];
    const int* edge_attr = (const int*)d_in[4];
    const float* W_conv  = (const float*)d_in[5];
    const float* b_conv  = (const float*)d_in[6];
    const float* W_mix   = (const float*)d_in[7];
    const float* b_mix   = (const float*)d_in[8];
    const float* W_ih    = (const float*)d_in[9];
    const float* W_hh    = (const float*)d_in[10];
    const float* b_ih    = (const float*)d_in[11];
    const float* b_hh    = (const float*)d_in[12];
    const float* W_ro    = (const float*)d_in[13];
    const float* b_ro    = (const float*)d_in[14];

    float* h_next = (float*)d_out;
    float* out3   = (float*)d_out + (size_t)NN * 64;

    k_zero_cnt<<<(NKB + 255) / 256, 256>>>();
    k_prep<<<162, 256>>>(W_conv, W_mix, b_mix, b_conv, W_ih, W_hh, b_ih, b_hh);
    k_hist<<<(NE + 255) / 256, 256>>>(node_idx, hedge_idx, edge_attr);
    k_offsets<<<NBA + NBB, 1024>>>();
    k_perm<<<(NE + 255) / 256, 256>>>(node_idx, hedge_idx, edge_attr);
    k_gatherA<<<(NKA * 32 + 255) / 256, 256>>>(x);
    k_mma_ef<<<dim3((NH + 127) / 128, 2), 256>>>();
    k_gatherB<<<(NN * 32 + 255) / 256, 256>>>();
    k_mma_gru<<<(NN + 127) / 128, 512>>>(h_prev, h_next);
    k_out<<<(NN + 127) / 128, 128>>>(h_next, W_ro, b_ro, out3);
}